// round 14
// baseline (speedup 1.0000x reference)
#include <cuda_runtime.h>
#include <cuda_fp16.h>
#include <cstdint>

// ============================================================================
// StagePolicyNetwork, K-reduced + merged bias table:
//   PDG[d*G+g] = b1 + h_dag[d]@W1[80:144] + h_glob[g]@W1[144:208]  (fp32)
//   main: gather(x,hn) -> [80x128] fp16 GEMM -> +PDG[bd*G+g], relu
//         -> [128x64] fp16 GEMM (fragment-major H, LDS.128) -> relu -> dot.
// Persistent CTAs, 512 threads, 128-row tiles, m16n8k16 fp32-accum.
// compute_103-safe (no tcgen05).
// ============================================================================

__device__ float g_PD[1024 * 128];
__device__ float g_PG[16 * 128];
__device__ float g_PDG[1024 * 16 * 128];   // 8 MB, L2-resident

__device__ __forceinline__ uint32_t pack_h2(float a, float b) {
    __half2 h = __floats2half2_rn(a, b);
    return *reinterpret_cast<uint32_t*>(&h);
}
__device__ __forceinline__ void mma_f16(float& c0, float& c1, float& c2, float& c3,
                                        uint32_t a0, uint32_t a1, uint32_t a2, uint32_t a3,
                                        uint32_t b0, uint32_t b1) {
    asm volatile(
        "mma.sync.aligned.m16n8k16.row.col.f32.f16.f16.f32 "
        "{%0,%1,%2,%3}, {%4,%5,%6,%7}, {%8,%9}, {%0,%1,%2,%3};"
        : "+f"(c0), "+f"(c1), "+f"(c2), "+f"(c3)
        : "r"(a0), "r"(a1), "r"(a2), "r"(a3), "r"(b0), "r"(b1));
}

// ---------------- constants --------------------------------------------------
static constexpr int TILE = 128;
static constexpr int NS1 = 5;           // 80/16 k-steps, layer 1 (x + h_node)
static constexpr int KS2 = 8;           // 128/16 k-steps, layer 2
static constexpr int RSTRIDE = 48;      // bytes per A row (32B data + 16B pad)
static constexpr int SSTRIDE = 128 * RSTRIDE;   // 6144 per k-step

// SMEM layout (bytes)
static constexpr int SM_W1F  = 0;        // 5*8*32*16  = 20480 (uint4 pairs)
static constexpr int SM_W2F  = 20480;    // 8*4*32*16  = 16384 (uint4 pairs)
static constexpr int SM_A    = 36864;    // 5*6144     = 30720
static constexpr int SM_H    = 67584;    // 8*8*32*16  = 32768 (fragment-major)
static constexpr int SM_B2   = 100352;   // 256
static constexpr int SM_W3   = 100608;   // 256
static constexpr int SM_PART = 100864;   // 128*4*4 = 2048
static constexpr int SM_CUM  = 102912;   // 128
static constexpr int SM_BDG  = 103040;   // 512 (per-row PDG row index)
static constexpr int SMEM_TOTAL = 103552;

// ---------------- precompute kernels ------------------------------------------
__global__ void precompute_pdg(const float* __restrict__ hd,
                               const float* __restrict__ hg,
                               const float* __restrict__ W1g,
                               const float* __restrict__ b1g,
                               int D, int G)
{
    const int c = threadIdx.x;           // 0..127
    const int r = blockIdx.x;
    if (r < D) {
        const float* v = hd + (size_t)r * 64;
        float s = 0.f;
        #pragma unroll 8
        for (int j = 0; j < 64; j++) s = fmaf(v[j], W1g[(80 + j) * 128 + c], s);
        g_PD[r * 128 + c] = s;
    } else {
        const int g = r - D;
        const float* v = hg + (size_t)g * 64;
        float s = b1g[c];
        #pragma unroll 8
        for (int j = 0; j < 64; j++) s = fmaf(v[j], W1g[(144 + j) * 128 + c], s);
        g_PG[g * 128 + c] = s;
    }
}

__global__ void combine_pdg(int G)
{
    const int idx = blockIdx.x;          // d*G + g
    const int c = threadIdx.x;
    const int d = idx / G, g = idx % G;
    g_PDG[(size_t)idx * 128 + c] = g_PD[d * 128 + c] + g_PG[g * 128 + c];
}

// ---------------- main kernel --------------------------------------------------
__global__ __launch_bounds__(512, 1)
void stage_policy_kernel(
    const float* __restrict__ x, const float* __restrict__ hn,
    const float* __restrict__ W1g,
    const float* __restrict__ W2g, const float* __restrict__ b2g,
    const float* __restrict__ W3g, const float* __restrict__ b3g,
    const int* __restrict__ stage_idx, const int* __restrict__ batch,
    const int* __restrict__ nsa,
    float* __restrict__ out, int M, int G, int ntiles)
{
    extern __shared__ char smem[];
    const int tid  = threadIdx.x;
    const int lane = tid & 31;
    const int g4   = lane >> 2;     // row within 8
    const int t4   = lane & 3;      // k/col pair
    const int wid  = tid >> 5;
    const int mg   = wid >> 2;      // rows 32*mg .. +32
    const int ng   = wid & 3;       // L1 cols 32*ng, L2 cols 16*ng

    float* sB2  = (float*)(smem + SM_B2);
    float* sW3  = (float*)(smem + SM_W3);
    float* sPt  = (float*)(smem + SM_PART);
    int*   sCum = (int*)(smem + SM_CUM);
    int*   sBDG = (int*)(smem + SM_BDG);

    // ---------------- one-time fills ----------------
    // W1 fragments, paired: [s(5)][nbp(8)][lane(32)] uint4 = {nb.b0,nb.b1,nb+1.b0,nb+1.b1}
    for (int i = tid; i < NS1 * 8 * 32; i += 512) {
        const int l = i & 31, nbp = (i >> 5) & 7, s = i >> 8;
        const int k0 = 16 * s + 2 * (l & 3);
        uint4 v;
        {
            const int col = 8 * (2 * nbp) + (l >> 2);
            v.x = pack_h2(W1g[k0 * 128 + col],       W1g[(k0 + 1) * 128 + col]);
            v.y = pack_h2(W1g[(k0 + 8) * 128 + col], W1g[(k0 + 9) * 128 + col]);
        }
        {
            const int col = 8 * (2 * nbp + 1) + (l >> 2);
            v.z = pack_h2(W1g[k0 * 128 + col],       W1g[(k0 + 1) * 128 + col]);
            v.w = pack_h2(W1g[(k0 + 8) * 128 + col], W1g[(k0 + 9) * 128 + col]);
        }
        ((uint4*)(smem + SM_W1F))[i] = v;
    }
    // W2 fragments, paired: [s(8)][nbp(4)][lane(32)] uint4
    for (int i = tid; i < KS2 * 4 * 32; i += 512) {
        const int l = i & 31, nbp = (i >> 5) & 3, s = i >> 7;
        const int k0 = 16 * s + 2 * (l & 3);
        uint4 v;
        {
            const int col = 8 * (2 * nbp) + (l >> 2);
            v.x = pack_h2(W2g[k0 * 64 + col],       W2g[(k0 + 1) * 64 + col]);
            v.y = pack_h2(W2g[(k0 + 8) * 64 + col], W2g[(k0 + 9) * 64 + col]);
        }
        {
            const int col = 8 * (2 * nbp + 1) + (l >> 2);
            v.z = pack_h2(W2g[k0 * 64 + col],       W2g[(k0 + 1) * 64 + col]);
            v.w = pack_h2(W2g[(k0 + 8) * 64 + col], W2g[(k0 + 9) * 64 + col]);
        }
        ((uint4*)(smem + SM_W2F))[i] = v;
    }
    if (tid >= 128 && tid < 192) sB2[tid - 128] = b2g[tid - 128];
    if (tid >= 192 && tid < 256) sW3[tid - 192] = W3g[tid - 192];
    if (tid == 0) {
        int c = 0; sCum[0] = 0;
        for (int i = 0; i < G; i++) { c += nsa[i]; sCum[i + 1] = c; }
    }
    const float b3v = b3g[0];
    __syncthreads();

    // gather role: 4 threads per row (grow in [0,128)); q = 4-col quarter
    const int grow = tid >> 2;      // 0..127
    const int q    = tid & 3;       // quarter within k-step (4 cols)

    // carried per-tile gather state (prefetched one tile ahead)
    int cidx, cpdg;
    {
        const int gr0 = blockIdx.x * TILE + grow;
        const int grc = (gr0 < M) ? gr0 : (M - 1);
        cidx = stage_idx[grc];
        const int cbd = batch[cidx];
        int g = 0;
        #pragma unroll 1
        while (g + 1 < G && grc >= sCum[g + 1]) g++;
        cpdg = cbd * G + g;
    }

    for (int tile = blockIdx.x; tile < ntiles; tile += gridDim.x) {
        const float* px  = x  + (size_t)cidx * 16;
        const float* phn = hn + (size_t)cidx * 64;

        // ---- gather: 5 k-steps, 1x LDG.128 -> fp16 -> STS.64 per step ----
        char* arow = smem + SM_A + grow * RSTRIDE + q * 8;
        #pragma unroll
        for (int j = 0; j < NS1; j++) {
            const int col = 16 * j + 4 * q;
            const float* p = (col < 16) ? (px + col) : (phn + (col - 16));
            const float4 v = *(const float4*)p;
            uint2 h;
            h.x = pack_h2(v.x, v.y);
            h.y = pack_h2(v.z, v.w);
            *(uint2*)(arow + j * SSTRIDE) = h;
        }
        if (q == 0) sBDG[grow] = cpdg;

        // prefetch next tile's indices (hidden under MMA phase)
        int nidx, npdg;
        {
            const int tn  = tile + gridDim.x;
            const int g0  = tn * TILE + grow;
            const int grn = (tn < ntiles) ? ((g0 < M) ? g0 : (M - 1)) : 0;
            nidx = stage_idx[grn];
            const int nbd = batch[nidx];
            int g = 0;
            #pragma unroll 1
            while (g + 1 < G && grn >= sCum[g + 1]) g++;
            npdg = nbd * G + g;
        }
        __syncthreads();   // bar 1: A + row-id table ready

        // ---------------- layer 1: 5 k-steps of m16n8k16 ----------------
        float acc[2][4][4];
        #pragma unroll
        for (int a = 0; a < 2; a++)
            #pragma unroll
            for (int b = 0; b < 4; b++)
                #pragma unroll
                for (int w = 0; w < 4; w++) acc[a][b][w] = 0.f;

        #pragma unroll
        for (int s = 0; s < NS1; s++) {
            uint32_t a[2][4];
            #pragma unroll
            for (int ml = 0; ml < 2; ml++) {
                const char* ap = smem + SM_A + s * SSTRIDE
                                 + (32 * mg + 16 * ml + g4) * RSTRIDE + t4 * 4;
                a[ml][0] = *(const uint32_t*)(ap);
                a[ml][1] = *(const uint32_t*)(ap + 8 * RSTRIDE);
                a[ml][2] = *(const uint32_t*)(ap + 16);
                a[ml][3] = *(const uint32_t*)(ap + 8 * RSTRIDE + 16);
            }
            const uint4 q0 = ((const uint4*)(smem + SM_W1F))[(s * 8 + 2 * ng) * 32 + lane];
            const uint4 q1 = ((const uint4*)(smem + SM_W1F))[(s * 8 + 2 * ng + 1) * 32 + lane];
            #pragma unroll
            for (int ml = 0; ml < 2; ml++) {
                mma_f16(acc[ml][0][0], acc[ml][0][1], acc[ml][0][2], acc[ml][0][3],
                        a[ml][0], a[ml][1], a[ml][2], a[ml][3], q0.x, q0.y);
                mma_f16(acc[ml][1][0], acc[ml][1][1], acc[ml][1][2], acc[ml][1][3],
                        a[ml][0], a[ml][1], a[ml][2], a[ml][3], q0.z, q0.w);
                mma_f16(acc[ml][2][0], acc[ml][2][1], acc[ml][2][2], acc[ml][2][3],
                        a[ml][0], a[ml][1], a[ml][2], a[ml][3], q1.x, q1.y);
                mma_f16(acc[ml][3][0], acc[ml][3][1], acc[ml][3][2], acc[ml][3][3],
                        a[ml][0], a[ml][1], a[ml][2], a[ml][3], q1.z, q1.w);
            }
        }

        // ---- epilogue 1: + PDG[bd*G+g] (fp32), relu, fp16 -> fragment-major H
        #pragma unroll
        for (int ml = 0; ml < 2; ml++) {
            const int r0 = 32 * mg + 16 * ml + g4;
            const int mf = 2 * mg + ml;          // m-fragment index 0..7
            const float* p0 = g_PDG + (size_t)sBDG[r0] * 128;
            const float* p1 = g_PDG + (size_t)sBDG[r0 + 8] * 128;
            #pragma unroll
            for (int j = 0; j < 2; j++) {
                const int s2 = 2 * ng + j;       // layer-2 k-step
                const int ce = 32 * ng + 16 * j + 2 * t4;   // nl = 2j
                const int co = ce + 8;                      // nl = 2j+1
                const float2 d0e = *(const float2*)(p0 + ce);
                const float2 d1e = *(const float2*)(p1 + ce);
                const float2 d0o = *(const float2*)(p0 + co);
                const float2 d1o = *(const float2*)(p1 + co);
                uint4 hv;
                hv.x = pack_h2(fmaxf(acc[ml][2*j][0] + d0e.x, 0.f),
                               fmaxf(acc[ml][2*j][1] + d0e.y, 0.f));      // a0
                hv.y = pack_h2(fmaxf(acc[ml][2*j][2] + d1e.x, 0.f),
                               fmaxf(acc[ml][2*j][3] + d1e.y, 0.f));      // a1
                hv.z = pack_h2(fmaxf(acc[ml][2*j+1][0] + d0o.x, 0.f),
                               fmaxf(acc[ml][2*j+1][1] + d0o.y, 0.f));    // a2
                hv.w = pack_h2(fmaxf(acc[ml][2*j+1][2] + d1o.x, 0.f),
                               fmaxf(acc[ml][2*j+1][3] + d1o.y, 0.f));    // a3
                ((uint4*)(smem + SM_H))[(s2 * 8 + mf) * 32 + lane] = hv;
            }
        }
        __syncthreads();   // bar 2: H ready

        // ---------------- layer 2: 8 k-steps, A via LDS.128 ----------------
        float ac2[2][2][4];
        #pragma unroll
        for (int a = 0; a < 2; a++)
            #pragma unroll
            for (int b = 0; b < 2; b++)
                #pragma unroll
                for (int w = 0; w < 4; w++) ac2[a][b][w] = 0.f;

        #pragma unroll
        for (int s = 0; s < KS2; s++) {
            const uint4 a0v = ((const uint4*)(smem + SM_H))[(s * 8 + 2 * mg) * 32 + lane];
            const uint4 a1v = ((const uint4*)(smem + SM_H))[(s * 8 + 2 * mg + 1) * 32 + lane];
            const uint4 bq  = ((const uint4*)(smem + SM_W2F))[(s * 4 + ng) * 32 + lane];
            mma_f16(ac2[0][0][0], ac2[0][0][1], ac2[0][0][2], ac2[0][0][3],
                    a0v.x, a0v.y, a0v.z, a0v.w, bq.x, bq.y);
            mma_f16(ac2[0][1][0], ac2[0][1][1], ac2[0][1][2], ac2[0][1][3],
                    a0v.x, a0v.y, a0v.z, a0v.w, bq.z, bq.w);
            mma_f16(ac2[1][0][0], ac2[1][0][1], ac2[1][0][2], ac2[1][0][3],
                    a1v.x, a1v.y, a1v.z, a1v.w, bq.x, bq.y);
            mma_f16(ac2[1][1][0], ac2[1][1][1], ac2[1][1][2], ac2[1][1][3],
                    a1v.x, a1v.y, a1v.z, a1v.w, bq.z, bq.w);
        }

        // ---- epilogue 2: +b2, relu, dot W3, reduce ----
        #pragma unroll
        for (int ml = 0; ml < 2; ml++) {
            float p0 = 0.f, p1 = 0.f;
            #pragma unroll
            for (int nl = 0; nl < 2; nl++) {
                const int col0 = 16 * ng + 8 * nl + 2 * t4;
                const float2 bb = *(const float2*)(sB2 + col0);
                const float2 ww = *(const float2*)(sW3 + col0);
                p0 += fmaxf(ac2[ml][nl][0] + bb.x, 0.f) * ww.x
                    + fmaxf(ac2[ml][nl][1] + bb.y, 0.f) * ww.y;
                p1 += fmaxf(ac2[ml][nl][2] + bb.x, 0.f) * ww.x
                    + fmaxf(ac2[ml][nl][3] + bb.y, 0.f) * ww.y;
            }
            p0 += __shfl_xor_sync(0xffffffffu, p0, 1);
            p0 += __shfl_xor_sync(0xffffffffu, p0, 2);
            p1 += __shfl_xor_sync(0xffffffffu, p1, 1);
            p1 += __shfl_xor_sync(0xffffffffu, p1, 2);
            if (t4 == 0) {
                const int r0 = 32 * mg + 16 * ml + g4;
                sPt[r0 * 4 + ng]       = p0;
                sPt[(r0 + 8) * 4 + ng] = p1;
            }
        }
        __syncthreads();   // bar 3: partials ready

        if (tid < 128) {
            const float4 p = ((const float4*)sPt)[tid];
            const int go = tile * TILE + tid;
            if (go < M) out[go] = p.x + p.y + p.z + p.w + b3v;
        }

        cidx = nidx; cpdg = npdg;
    }
}

// ---------------------------------------------------------------------------
extern "C" void kernel_launch(void* const* d_in, const int* in_sizes, int n_in,
                              void* d_out, int out_size) {
    const float* x   = (const float*)d_in[0];
    const float* hn  = (const float*)d_in[1];
    const float* hd  = (const float*)d_in[2];
    const float* hg  = (const float*)d_in[3];
    const float* W1  = (const float*)d_in[4];
    const float* b1  = (const float*)d_in[5];
    const float* W2  = (const float*)d_in[6];
    const float* b2  = (const float*)d_in[7];
    const float* W3  = (const float*)d_in[8];
    const float* b3  = (const float*)d_in[9];
    const int* sidx  = (const int*)d_in[10];
    const int* batch = (const int*)d_in[11];
    const int* nsa   = (const int*)d_in[12];
    float* out = (float*)d_out;

    const int M = in_sizes[10];
    const int G = in_sizes[12];
    int D = in_sizes[2] / 64;
    if (D > 1024) D = 1024;
    int Gc = G; if (Gc > 16) Gc = 16;
    const int ntiles = (M + TILE - 1) / TILE;

    static int sms = 0;
    if (sms == 0) {
        cudaDeviceGetAttribute(&sms, cudaDevAttrMultiProcessorCount, 0);
        cudaFuncSetAttribute(stage_policy_kernel,
                             cudaFuncAttributeMaxDynamicSharedMemorySize, SMEM_TOTAL);
        if (sms <= 0) sms = 148;
    }
    const int grid = (ntiles < sms) ? ntiles : sms;

    precompute_pdg<<<D + Gc, 128>>>(hd, hg, W1, b1, D, Gc);
    combine_pdg<<<D * Gc, 128>>>(Gc);
    stage_policy_kernel<<<grid, 512, SMEM_TOTAL>>>(
        x, hn, W1, W2, b2, W3, b3, sidx, batch, nsa, out, M, G, ntiles);
}

// round 15
// speedup vs baseline: 1.0236x; 1.0236x over previous
#include <cuda_runtime.h>
#include <cuda_fp16.h>
#include <cstdint>

// ============================================================================
// StagePolicyNetwork, K-reduced:
//   PD[d] = h_dag[d]@W1[80:144]                  (precomputed, fp32, global)
//   PG[g] = b1 + h_glob[g]@W1[144:208]           (precomputed, fp32 -> SMEM)
//   main: gather(x,hn) -> [80x128] fp16 GEMM -> +PD[bd]+PG[g], relu
//         -> [128x64] fp16 GEMM (fragment-major H, LDS.128) -> relu -> dot.
// Persistent CTAs, 512 threads, 128-row tiles, m16n8k16 fp32-accum.
// compute_103-safe (no tcgen05).
// ============================================================================

__device__ float g_PD[1024 * 128];
__device__ float g_PG[16 * 128];

__device__ __forceinline__ uint32_t pack_h2(float a, float b) {
    __half2 h = __floats2half2_rn(a, b);
    return *reinterpret_cast<uint32_t*>(&h);
}
__device__ __forceinline__ void mma_f16(float& c0, float& c1, float& c2, float& c3,
                                        uint32_t a0, uint32_t a1, uint32_t a2, uint32_t a3,
                                        uint32_t b0, uint32_t b1) {
    asm volatile(
        "mma.sync.aligned.m16n8k16.row.col.f32.f16.f16.f32 "
        "{%0,%1,%2,%3}, {%4,%5,%6,%7}, {%8,%9}, {%0,%1,%2,%3};"
        : "+f"(c0), "+f"(c1), "+f"(c2), "+f"(c3)
        : "r"(a0), "r"(a1), "r"(a2), "r"(a3), "r"(b0), "r"(b1));
}

// ---------------- constants --------------------------------------------------
static constexpr int TILE = 128;
static constexpr int NS1 = 5;           // 80/16 k-steps, layer 1 (x + h_node)
static constexpr int KS2 = 8;           // 128/16 k-steps, layer 2
static constexpr int RSTRIDE = 48;      // bytes per A row (32B data + 16B pad)
static constexpr int SSTRIDE = 128 * RSTRIDE;   // 6144 per k-step

// SMEM layout (bytes)
static constexpr int SM_W1F  = 0;        // 5*8*32*16  = 20480 (uint4 pairs)
static constexpr int SM_W2F  = 20480;    // 8*4*32*16  = 16384 (uint4 pairs)
static constexpr int SM_A    = 36864;    // 5*6144     = 30720
static constexpr int SM_H    = 67584;    // 8*8*32*16  = 32768 (fragment-major)
static constexpr int SM_PG   = 100352;   // 16*128*4   = 8192
static constexpr int SM_B2   = 108544;   // 256
static constexpr int SM_W3   = 108800;   // 256
static constexpr int SM_PART = 109056;   // 128*4*4 = 2048
static constexpr int SM_CUM  = 111104;   // 128
static constexpr int SM_BD   = 111232;   // 512 (per-row dag id)
static constexpr int SM_G    = 111744;   // 512 (per-row glob id)
static constexpr int SMEM_TOTAL = 112256;

// ---------------- precompute kernel ------------------------------------------
__global__ void precompute_pdg(const float* __restrict__ hd,
                               const float* __restrict__ hg,
                               const float* __restrict__ W1g,
                               const float* __restrict__ b1g,
                               int D, int G)
{
    const int c = threadIdx.x;           // 0..127
    const int r = blockIdx.x;
    if (r < D) {
        const float* v = hd + (size_t)r * 64;
        float s = 0.f;
        #pragma unroll 8
        for (int j = 0; j < 64; j++) s = fmaf(v[j], W1g[(80 + j) * 128 + c], s);
        g_PD[r * 128 + c] = s;
    } else {
        const int g = r - D;
        const float* v = hg + (size_t)g * 64;
        float s = b1g[c];
        #pragma unroll 8
        for (int j = 0; j < 64; j++) s = fmaf(v[j], W1g[(144 + j) * 128 + c], s);
        g_PG[g * 128 + c] = s;
    }
}

// ---------------- main kernel --------------------------------------------------
__global__ __launch_bounds__(512, 1)
void stage_policy_kernel(
    const float* __restrict__ x, const float* __restrict__ hn,
    const float* __restrict__ W1g,
    const float* __restrict__ W2g, const float* __restrict__ b2g,
    const float* __restrict__ W3g, const float* __restrict__ b3g,
    const int* __restrict__ stage_idx, const int* __restrict__ batch,
    const int* __restrict__ nsa,
    float* __restrict__ out, int M, int G, int ntiles)
{
    extern __shared__ char smem[];
    const int tid  = threadIdx.x;
    const int lane = tid & 31;
    const int g4   = lane >> 2;     // row within 8
    const int t4   = lane & 3;      // k/col pair
    const int wid  = tid >> 5;
    const int mg   = wid >> 2;      // rows 32*mg .. +32
    const int ng   = wid & 3;       // L1 cols 32*ng, L2 cols 16*ng

    float* sPG  = (float*)(smem + SM_PG);
    float* sB2  = (float*)(smem + SM_B2);
    float* sW3  = (float*)(smem + SM_W3);
    float* sPt  = (float*)(smem + SM_PART);
    int*   sCum = (int*)(smem + SM_CUM);
    int*   sBD  = (int*)(smem + SM_BD);
    int*   sG   = (int*)(smem + SM_G);

    // ---------------- one-time fills ----------------
    // W1 fragments, paired: [s(5)][nbp(8)][lane(32)] uint4 = {nb.b0,nb.b1,nb+1.b0,nb+1.b1}
    for (int i = tid; i < NS1 * 8 * 32; i += 512) {
        const int l = i & 31, nbp = (i >> 5) & 7, s = i >> 8;
        const int k0 = 16 * s + 2 * (l & 3);
        uint4 v;
        {
            const int col = 8 * (2 * nbp) + (l >> 2);
            v.x = pack_h2(W1g[k0 * 128 + col],       W1g[(k0 + 1) * 128 + col]);
            v.y = pack_h2(W1g[(k0 + 8) * 128 + col], W1g[(k0 + 9) * 128 + col]);
        }
        {
            const int col = 8 * (2 * nbp + 1) + (l >> 2);
            v.z = pack_h2(W1g[k0 * 128 + col],       W1g[(k0 + 1) * 128 + col]);
            v.w = pack_h2(W1g[(k0 + 8) * 128 + col], W1g[(k0 + 9) * 128 + col]);
        }
        ((uint4*)(smem + SM_W1F))[i] = v;
    }
    // W2 fragments, paired: [s(8)][nbp(4)][lane(32)] uint4
    for (int i = tid; i < KS2 * 4 * 32; i += 512) {
        const int l = i & 31, nbp = (i >> 5) & 3, s = i >> 7;
        const int k0 = 16 * s + 2 * (l & 3);
        uint4 v;
        {
            const int col = 8 * (2 * nbp) + (l >> 2);
            v.x = pack_h2(W2g[k0 * 64 + col],       W2g[(k0 + 1) * 64 + col]);
            v.y = pack_h2(W2g[(k0 + 8) * 64 + col], W2g[(k0 + 9) * 64 + col]);
        }
        {
            const int col = 8 * (2 * nbp + 1) + (l >> 2);
            v.z = pack_h2(W2g[k0 * 64 + col],       W2g[(k0 + 1) * 64 + col]);
            v.w = pack_h2(W2g[(k0 + 8) * 64 + col], W2g[(k0 + 9) * 64 + col]);
        }
        ((uint4*)(smem + SM_W2F))[i] = v;
    }
    // PG table -> SMEM (written by precompute kernel, prior launch)
    for (int i = tid; i < 16 * 128 / 4; i += 512)
        ((float4*)sPG)[i] = ((const float4*)g_PG)[i];
    if (tid >= 128 && tid < 192) sB2[tid - 128] = b2g[tid - 128];
    if (tid >= 192 && tid < 256) sW3[tid - 192] = W3g[tid - 192];
    if (tid == 0) {
        int c = 0; sCum[0] = 0;
        for (int i = 0; i < G; i++) { c += nsa[i]; sCum[i + 1] = c; }
    }
    const float b3v = b3g[0];
    __syncthreads();

    // gather role: 4 threads per row (grow in [0,128)); q = 4-col quarter
    const int grow = tid >> 2;      // 0..127
    const int q    = tid & 3;       // quarter within k-step (4 cols)

    // carried per-tile gather state (prefetched one tile ahead)
    int cidx, cbd, cgg;
    {
        const int gr0 = blockIdx.x * TILE + grow;
        const int grc = (gr0 < M) ? gr0 : (M - 1);
        cidx = stage_idx[grc];
        cbd  = batch[cidx];
        int g = 0;
        #pragma unroll 1
        while (g + 1 < G && grc >= sCum[g + 1]) g++;
        cgg = g;
    }

    for (int tile = blockIdx.x; tile < ntiles; tile += gridDim.x) {
        const float* px  = x  + (size_t)cidx * 16;
        const float* phn = hn + (size_t)cidx * 64;

        // ---- gather: 5 k-steps, 1x LDG.128 -> fp16 -> STS.64 per step ----
        char* arow = smem + SM_A + grow * RSTRIDE + q * 8;
        #pragma unroll
        for (int j = 0; j < NS1; j++) {
            const int col = 16 * j + 4 * q;
            const float* p = (col < 16) ? (px + col) : (phn + (col - 16));
            const float4 v = *(const float4*)p;
            uint2 h;
            h.x = pack_h2(v.x, v.y);
            h.y = pack_h2(v.z, v.w);
            *(uint2*)(arow + j * SSTRIDE) = h;
        }
        if (q == 0) { sBD[grow] = cbd; sG[grow] = cgg; }

        // prefetch next tile's indices (hidden under MMA phase)
        int nidx, nbd, ngg;
        {
            const int tn  = tile + gridDim.x;
            const int g0  = tn * TILE + grow;
            const int grn = (tn < ntiles) ? ((g0 < M) ? g0 : (M - 1)) : 0;
            nidx = stage_idx[grn];
            nbd  = batch[nidx];
            int g = 0;
            #pragma unroll 1
            while (g + 1 < G && grn >= sCum[g + 1]) g++;
            ngg = g;
        }
        __syncthreads();   // bar 1: A + row-id tables ready

        // ---------------- layer 1: 5 k-steps of m16n8k16 ----------------
        float acc[2][4][4];
        #pragma unroll
        for (int a = 0; a < 2; a++)
            #pragma unroll
            for (int b = 0; b < 4; b++)
                #pragma unroll
                for (int w = 0; w < 4; w++) acc[a][b][w] = 0.f;

        #pragma unroll
        for (int s = 0; s < NS1; s++) {
            uint32_t a[2][4];
            #pragma unroll
            for (int ml = 0; ml < 2; ml++) {
                const char* ap = smem + SM_A + s * SSTRIDE
                                 + (32 * mg + 16 * ml + g4) * RSTRIDE + t4 * 4;
                a[ml][0] = *(const uint32_t*)(ap);
                a[ml][1] = *(const uint32_t*)(ap + 8 * RSTRIDE);
                a[ml][2] = *(const uint32_t*)(ap + 16);
                a[ml][3] = *(const uint32_t*)(ap + 8 * RSTRIDE + 16);
            }
            const uint4 q0 = ((const uint4*)(smem + SM_W1F))[(s * 8 + 2 * ng) * 32 + lane];
            const uint4 q1 = ((const uint4*)(smem + SM_W1F))[(s * 8 + 2 * ng + 1) * 32 + lane];
            #pragma unroll
            for (int ml = 0; ml < 2; ml++) {
                mma_f16(acc[ml][0][0], acc[ml][0][1], acc[ml][0][2], acc[ml][0][3],
                        a[ml][0], a[ml][1], a[ml][2], a[ml][3], q0.x, q0.y);
                mma_f16(acc[ml][1][0], acc[ml][1][1], acc[ml][1][2], acc[ml][1][3],
                        a[ml][0], a[ml][1], a[ml][2], a[ml][3], q0.z, q0.w);
                mma_f16(acc[ml][2][0], acc[ml][2][1], acc[ml][2][2], acc[ml][2][3],
                        a[ml][0], a[ml][1], a[ml][2], a[ml][3], q1.x, q1.y);
                mma_f16(acc[ml][3][0], acc[ml][3][1], acc[ml][3][2], acc[ml][3][3],
                        a[ml][0], a[ml][1], a[ml][2], a[ml][3], q1.z, q1.w);
            }
        }

        // ---- epilogue 1: + PD[bd] (global) + PG[g] (smem), relu,
        //      fp16 -> fragment-major H
        #pragma unroll
        for (int ml = 0; ml < 2; ml++) {
            const int r0 = 32 * mg + 16 * ml + g4;
            const int mf = 2 * mg + ml;          // m-fragment index 0..7
            const float* p0 = g_PD + (size_t)sBD[r0] * 128;
            const float* p1 = g_PD + (size_t)sBD[r0 + 8] * 128;
            const float* e0 = sPG + sG[r0] * 128;
            const float* e1 = sPG + sG[r0 + 8] * 128;
            #pragma unroll
            for (int j = 0; j < 2; j++) {
                const int s2 = 2 * ng + j;       // layer-2 k-step
                const int ce = 32 * ng + 16 * j + 2 * t4;   // nl = 2j
                const int co = ce + 8;                      // nl = 2j+1
                const float2 d0e = *(const float2*)(p0 + ce);
                const float2 d1e = *(const float2*)(p1 + ce);
                const float2 d0o = *(const float2*)(p0 + co);
                const float2 d1o = *(const float2*)(p1 + co);
                const float2 g0e = *(const float2*)(e0 + ce);
                const float2 g1e = *(const float2*)(e1 + ce);
                const float2 g0o = *(const float2*)(e0 + co);
                const float2 g1o = *(const float2*)(e1 + co);
                uint4 hv;
                hv.x = pack_h2(fmaxf(acc[ml][2*j][0] + d0e.x + g0e.x, 0.f),
                               fmaxf(acc[ml][2*j][1] + d0e.y + g0e.y, 0.f));    // a0
                hv.y = pack_h2(fmaxf(acc[ml][2*j][2] + d1e.x + g1e.x, 0.f),
                               fmaxf(acc[ml][2*j][3] + d1e.y + g1e.y, 0.f));    // a1
                hv.z = pack_h2(fmaxf(acc[ml][2*j+1][0] + d0o.x + g0o.x, 0.f),
                               fmaxf(acc[ml][2*j+1][1] + d0o.y + g0o.y, 0.f));  // a2
                hv.w = pack_h2(fmaxf(acc[ml][2*j+1][2] + d1o.x + g1o.x, 0.f),
                               fmaxf(acc[ml][2*j+1][3] + d1o.y + g1o.y, 0.f));  // a3
                ((uint4*)(smem + SM_H))[(s2 * 8 + mf) * 32 + lane] = hv;
            }
        }
        __syncthreads();   // bar 2: H ready

        // ---------------- layer 2: 8 k-steps, A via LDS.128 ----------------
        float ac2[2][2][4];
        #pragma unroll
        for (int a = 0; a < 2; a++)
            #pragma unroll
            for (int b = 0; b < 2; b++)
                #pragma unroll
                for (int w = 0; w < 4; w++) ac2[a][b][w] = 0.f;

        #pragma unroll
        for (int s = 0; s < KS2; s++) {
            const uint4 a0v = ((const uint4*)(smem + SM_H))[(s * 8 + 2 * mg) * 32 + lane];
            const uint4 a1v = ((const uint4*)(smem + SM_H))[(s * 8 + 2 * mg + 1) * 32 + lane];
            const uint4 bq  = ((const uint4*)(smem + SM_W2F))[(s * 4 + ng) * 32 + lane];
            mma_f16(ac2[0][0][0], ac2[0][0][1], ac2[0][0][2], ac2[0][0][3],
                    a0v.x, a0v.y, a0v.z, a0v.w, bq.x, bq.y);
            mma_f16(ac2[0][1][0], ac2[0][1][1], ac2[0][1][2], ac2[0][1][3],
                    a0v.x, a0v.y, a0v.z, a0v.w, bq.z, bq.w);
            mma_f16(ac2[1][0][0], ac2[1][0][1], ac2[1][0][2], ac2[1][0][3],
                    a1v.x, a1v.y, a1v.z, a1v.w, bq.x, bq.y);
            mma_f16(ac2[1][1][0], ac2[1][1][1], ac2[1][1][2], ac2[1][1][3],
                    a1v.x, a1v.y, a1v.z, a1v.w, bq.z, bq.w);
        }

        // ---- epilogue 2: +b2, relu, dot W3, reduce ----
        #pragma unroll
        for (int ml = 0; ml < 2; ml++) {
            float p0 = 0.f, p1 = 0.f;
            #pragma unroll
            for (int nl = 0; nl < 2; nl++) {
                const int col0 = 16 * ng + 8 * nl + 2 * t4;
                const float2 bb = *(const float2*)(sB2 + col0);
                const float2 ww = *(const float2*)(sW3 + col0);
                p0 += fmaxf(ac2[ml][nl][0] + bb.x, 0.f) * ww.x
                    + fmaxf(ac2[ml][nl][1] + bb.y, 0.f) * ww.y;
                p1 += fmaxf(ac2[ml][nl][2] + bb.x, 0.f) * ww.x
                    + fmaxf(ac2[ml][nl][3] + bb.y, 0.f) * ww.y;
            }
            p0 += __shfl_xor_sync(0xffffffffu, p0, 1);
            p0 += __shfl_xor_sync(0xffffffffu, p0, 2);
            p1 += __shfl_xor_sync(0xffffffffu, p1, 1);
            p1 += __shfl_xor_sync(0xffffffffu, p1, 2);
            if (t4 == 0) {
                const int r0 = 32 * mg + 16 * ml + g4;
                sPt[r0 * 4 + ng]       = p0;
                sPt[(r0 + 8) * 4 + ng] = p1;
            }
        }
        __syncthreads();   // bar 3: partials ready

        if (tid < 128) {
            const float4 p = ((const float4*)sPt)[tid];
            const int go = tile * TILE + tid;
            if (go < M) out[go] = p.x + p.y + p.z + p.w + b3v;
        }

        cidx = nidx; cbd = nbd; cgg = ngg;
    }
}

// ---------------------------------------------------------------------------
extern "C" void kernel_launch(void* const* d_in, const int* in_sizes, int n_in,
                              void* d_out, int out_size) {
    const float* x   = (const float*)d_in[0];
    const float* hn  = (const float*)d_in[1];
    const float* hd  = (const float*)d_in[2];
    const float* hg  = (const float*)d_in[3];
    const float* W1  = (const float*)d_in[4];
    const float* b1  = (const float*)d_in[5];
    const float* W2  = (const float*)d_in[6];
    const float* b2  = (const float*)d_in[7];
    const float* W3  = (const float*)d_in[8];
    const float* b3  = (const float*)d_in[9];
    const int* sidx  = (const int*)d_in[10];
    const int* batch = (const int*)d_in[11];
    const int* nsa   = (const int*)d_in[12];
    float* out = (float*)d_out;

    const int M = in_sizes[10];
    const int G = in_sizes[12];
    int D = in_sizes[2] / 64;
    if (D > 1024) D = 1024;
    int Gc = G; if (Gc > 16) Gc = 16;
    const int ntiles = (M + TILE - 1) / TILE;

    static int sms = 0;
    if (sms == 0) {
        cudaDeviceGetAttribute(&sms, cudaDevAttrMultiProcessorCount, 0);
        cudaFuncSetAttribute(stage_policy_kernel,
                             cudaFuncAttributeMaxDynamicSharedMemorySize, SMEM_TOTAL);
        if (sms <= 0) sms = 148;
    }
    const int grid = (ntiles < sms) ? ntiles : sms;

    precompute_pdg<<<D + Gc, 128>>>(hd, hg, W1, b1, D, Gc);
    stage_policy_kernel<<<grid, 512, SMEM_TOTAL>>>(
        x, hn, W1, W2, b2, W3, b3, sidx, batch, nsa, out, M, G, ntiles);
}

// round 16
// speedup vs baseline: 1.0985x; 1.0732x over previous
#include <cuda_runtime.h>
#include <cuda_fp16.h>
#include <cstdint>

// ============================================================================
// StagePolicyNetwork, K-reduced, DUAL-PIPELINE:
//   PD[d] = h_dag[d]@W1[80:144]        (precomputed fp32, global/L2)
//   PG[g] = b1 + h_glob[g]@W1[144:208] (precomputed fp32 -> SMEM)
//   main: 512 threads = TWO independent 256-thread pipelines (named barriers),
//   64-row tiles each:  gather(x,hn) -> [80x64] fp16 GEMM -> +PD+PG, relu
//         -> [128x64] fp16 GEMM (fragment-major H) -> relu -> dot.
// compute_103-safe (no tcgen05).
// ============================================================================

__device__ float g_PD[1024 * 128];
__device__ float g_PG[16 * 128];

__device__ __forceinline__ uint32_t pack_h2(float a, float b) {
    __half2 h = __floats2half2_rn(a, b);
    return *reinterpret_cast<uint32_t*>(&h);
}
__device__ __forceinline__ void hbar(int barid) {
    asm volatile("bar.sync %0, 256;" :: "r"(barid) : "memory");
}
__device__ __forceinline__ void mma_f16(float& c0, float& c1, float& c2, float& c3,
                                        uint32_t a0, uint32_t a1, uint32_t a2, uint32_t a3,
                                        uint32_t b0, uint32_t b1) {
    asm volatile(
        "mma.sync.aligned.m16n8k16.row.col.f32.f16.f16.f32 "
        "{%0,%1,%2,%3}, {%4,%5,%6,%7}, {%8,%9}, {%0,%1,%2,%3};"
        : "+f"(c0), "+f"(c1), "+f"(c2), "+f"(c3)
        : "r"(a0), "r"(a1), "r"(a2), "r"(a3), "r"(b0), "r"(b1));
}

// ---------------- constants --------------------------------------------------
static constexpr int TILE = 64;         // rows per pipeline tile
static constexpr int NS1 = 5;           // 80/16 k-steps, layer 1 (x + h_node)
static constexpr int KS2 = 8;           // 128/16 k-steps, layer 2
static constexpr int RSTRIDE = 48;      // bytes per A row (32B data + 16B pad)
static constexpr int SSTRIDE = 64 * RSTRIDE;    // 3072 per k-step (64 rows)

// SMEM layout (bytes)
static constexpr int SM_W1F = 0;        // 5*8*32*16 = 20480 (uint4 pairs)
static constexpr int SM_W2F = 20480;    // 8*4*32*16 = 16384 (uint4 pairs)
static constexpr int SM_PG  = 36864;    // 16*128*4  = 8192
static constexpr int SM_B2  = 45056;    // 256
static constexpr int SM_W3  = 45312;    // 256
static constexpr int SM_CUM = 45568;    // 128
// per-half regions (half stride = 33280)
static constexpr int SM_A0  = 46080;    // 5*3072 = 15360
static constexpr int SM_H0  = 61440;    // 8*4*32*16 = 16384 (fragment-major)
static constexpr int SM_PT0 = 77824;    // 64*4*4 = 1024
static constexpr int SM_BD0 = 78848;    // 256
static constexpr int SM_G0  = 79104;    // 256
static constexpr int HALF_STRIDE = 33280;
static constexpr int SMEM_TOTAL = 46080 + 2 * HALF_STRIDE;   // 112640

// ---------------- precompute kernel ------------------------------------------
__global__ void precompute_pdg(const float* __restrict__ hd,
                               const float* __restrict__ hg,
                               const float* __restrict__ W1g,
                               const float* __restrict__ b1g,
                               int D, int G)
{
    const int c = threadIdx.x;           // 0..127
    const int r = blockIdx.x;
    if (r < D) {
        const float* v = hd + (size_t)r * 64;
        float s = 0.f;
        #pragma unroll 8
        for (int j = 0; j < 64; j++) s = fmaf(v[j], W1g[(80 + j) * 128 + c], s);
        g_PD[r * 128 + c] = s;
    } else {
        const int g = r - D;
        const float* v = hg + (size_t)g * 64;
        float s = b1g[c];
        #pragma unroll 8
        for (int j = 0; j < 64; j++) s = fmaf(v[j], W1g[(144 + j) * 128 + c], s);
        g_PG[g * 128 + c] = s;
    }
}

// ---------------- main kernel --------------------------------------------------
__global__ __launch_bounds__(512, 1)
void stage_policy_kernel(
    const float* __restrict__ x, const float* __restrict__ hn,
    const float* __restrict__ W1g,
    const float* __restrict__ W2g, const float* __restrict__ b2g,
    const float* __restrict__ W3g, const float* __restrict__ b3g,
    const int* __restrict__ stage_idx, const int* __restrict__ batch,
    const int* __restrict__ nsa,
    float* __restrict__ out, int M, int G, int ntiles)
{
    extern __shared__ char smem[];
    const int tid  = threadIdx.x;
    const int lane = tid & 31;
    const int g4   = lane >> 2;     // row within 8
    const int t4   = lane & 3;      // k/col pair
    const int halfid = tid >> 8;    // 0: warps 0-7, 1: warps 8-15
    const int htid = tid & 255;
    const int hwid = htid >> 5;     // warp within half, 0..7
    const int mg   = hwid >> 2;     // rows 32*mg .. +32 (of 64)
    const int ng   = hwid & 3;      // L1 cols 32*ng, L2 cols 16*ng
    const int barid = 1 + halfid;

    const int HB = halfid * HALF_STRIDE;
    char* sA = smem + SM_A0 + HB;
    char* sH = smem + SM_H0 + HB;
    float* sPG  = (float*)(smem + SM_PG);
    float* sB2  = (float*)(smem + SM_B2);
    float* sW3  = (float*)(smem + SM_W3);
    float* sPt  = (float*)(smem + SM_PT0 + HB);
    int*   sCum = (int*)(smem + SM_CUM);
    int*   sBD  = (int*)(smem + SM_BD0 + HB);
    int*   sG   = (int*)(smem + SM_G0 + HB);

    // ---------------- one-time fills (whole CTA) ----------------
    // W1 fragments, paired: [s(5)][nbp(8)][lane(32)] uint4
    for (int i = tid; i < NS1 * 8 * 32; i += 512) {
        const int l = i & 31, nbp = (i >> 5) & 7, s = i >> 8;
        const int k0 = 16 * s + 2 * (l & 3);
        uint4 v;
        {
            const int col = 8 * (2 * nbp) + (l >> 2);
            v.x = pack_h2(W1g[k0 * 128 + col],       W1g[(k0 + 1) * 128 + col]);
            v.y = pack_h2(W1g[(k0 + 8) * 128 + col], W1g[(k0 + 9) * 128 + col]);
        }
        {
            const int col = 8 * (2 * nbp + 1) + (l >> 2);
            v.z = pack_h2(W1g[k0 * 128 + col],       W1g[(k0 + 1) * 128 + col]);
            v.w = pack_h2(W1g[(k0 + 8) * 128 + col], W1g[(k0 + 9) * 128 + col]);
        }
        ((uint4*)(smem + SM_W1F))[i] = v;
    }
    // W2 fragments, paired: [s(8)][nbp(4)][lane(32)] uint4
    for (int i = tid; i < KS2 * 4 * 32; i += 512) {
        const int l = i & 31, nbp = (i >> 5) & 3, s = i >> 7;
        const int k0 = 16 * s + 2 * (l & 3);
        uint4 v;
        {
            const int col = 8 * (2 * nbp) + (l >> 2);
            v.x = pack_h2(W2g[k0 * 64 + col],       W2g[(k0 + 1) * 64 + col]);
            v.y = pack_h2(W2g[(k0 + 8) * 64 + col], W2g[(k0 + 9) * 64 + col]);
        }
        {
            const int col = 8 * (2 * nbp + 1) + (l >> 2);
            v.z = pack_h2(W2g[k0 * 64 + col],       W2g[(k0 + 1) * 64 + col]);
            v.w = pack_h2(W2g[(k0 + 8) * 64 + col], W2g[(k0 + 9) * 64 + col]);
        }
        ((uint4*)(smem + SM_W2F))[i] = v;
    }
    // PG table -> SMEM
    for (int i = tid; i < 16 * 128 / 4; i += 512)
        ((float4*)sPG)[i] = ((const float4*)g_PG)[i];
    if (tid >= 128 && tid < 192) sB2[tid - 128] = b2g[tid - 128];
    if (tid >= 192 && tid < 256) sW3[tid - 192] = W3g[tid - 192];
    if (tid == 0) {
        int c = 0; sCum[0] = 0;
        for (int i = 0; i < G; i++) { c += nsa[i]; sCum[i + 1] = c; }
    }
    const float b3v = b3g[0];
    __syncthreads();

    // gather role within half: 4 threads per row (grow in [0,64)); q = quarter
    const int grow = htid >> 2;     // 0..63
    const int q    = htid & 3;

    const int tstride = 2 * gridDim.x;
    const int tile0   = 2 * blockIdx.x + halfid;

    // carried per-tile gather state (prefetched one tile ahead)
    int cidx, cbd, cgg;
    {
        const int gr0 = tile0 * TILE + grow;
        const int grc = (gr0 < M) ? gr0 : (M - 1);
        cidx = stage_idx[grc];
        cbd  = batch[cidx];
        int g = 0;
        #pragma unroll 1
        while (g + 1 < G && grc >= sCum[g + 1]) g++;
        cgg = g;
    }

    for (int tile = tile0; tile < ntiles; tile += tstride) {
        const float* px  = x  + (size_t)cidx * 16;
        const float* phn = hn + (size_t)cidx * 64;

        // ---- gather: 5 k-steps, 1x LDG.128 -> fp16 -> STS.64 per step ----
        char* arow = sA + grow * RSTRIDE + q * 8;
        #pragma unroll
        for (int j = 0; j < NS1; j++) {
            const int col = 16 * j + 4 * q;
            const float* p = (col < 16) ? (px + col) : (phn + (col - 16));
            const float4 v = *(const float4*)p;
            uint2 h;
            h.x = pack_h2(v.x, v.y);
            h.y = pack_h2(v.z, v.w);
            *(uint2*)(arow + j * SSTRIDE) = h;
        }
        if (q == 0) { sBD[grow] = cbd; sG[grow] = cgg; }

        // prefetch next tile's indices (hidden under MMA phase)
        int nidx, nbd, ngg;
        {
            const int tn  = tile + tstride;
            const int g0  = tn * TILE + grow;
            const int grn = (tn < ntiles) ? ((g0 < M) ? g0 : (M - 1)) : 0;
            nidx = stage_idx[grn];
            nbd  = batch[nidx];
            int g = 0;
            #pragma unroll 1
            while (g + 1 < G && grn >= sCum[g + 1]) g++;
            ngg = g;
        }
        hbar(barid);   // bar 1: A + row-id tables ready

        // ---------------- layer 1: 5 k-steps of m16n8k16 ----------------
        float acc[2][4][4];
        #pragma unroll
        for (int a = 0; a < 2; a++)
            #pragma unroll
            for (int b = 0; b < 4; b++)
                #pragma unroll
                for (int w = 0; w < 4; w++) acc[a][b][w] = 0.f;

        #pragma unroll
        for (int s = 0; s < NS1; s++) {
            uint32_t a[2][4];
            #pragma unroll
            for (int ml = 0; ml < 2; ml++) {
                const char* ap = sA + s * SSTRIDE
                                 + (32 * mg + 16 * ml + g4) * RSTRIDE + t4 * 4;
                a[ml][0] = *(const uint32_t*)(ap);
                a[ml][1] = *(const uint32_t*)(ap + 8 * RSTRIDE);
                a[ml][2] = *(const uint32_t*)(ap + 16);
                a[ml][3] = *(const uint32_t*)(ap + 8 * RSTRIDE + 16);
            }
            const uint4 q0 = ((const uint4*)(smem + SM_W1F))[(s * 8 + 2 * ng) * 32 + lane];
            const uint4 q1 = ((const uint4*)(smem + SM_W1F))[(s * 8 + 2 * ng + 1) * 32 + lane];
            #pragma unroll
            for (int ml = 0; ml < 2; ml++) {
                mma_f16(acc[ml][0][0], acc[ml][0][1], acc[ml][0][2], acc[ml][0][3],
                        a[ml][0], a[ml][1], a[ml][2], a[ml][3], q0.x, q0.y);
                mma_f16(acc[ml][1][0], acc[ml][1][1], acc[ml][1][2], acc[ml][1][3],
                        a[ml][0], a[ml][1], a[ml][2], a[ml][3], q0.z, q0.w);
                mma_f16(acc[ml][2][0], acc[ml][2][1], acc[ml][2][2], acc[ml][2][3],
                        a[ml][0], a[ml][1], a[ml][2], a[ml][3], q1.x, q1.y);
                mma_f16(acc[ml][3][0], acc[ml][3][1], acc[ml][3][2], acc[ml][3][3],
                        a[ml][0], a[ml][1], a[ml][2], a[ml][3], q1.z, q1.w);
            }
        }

        // ---- epilogue 1: + PD[bd] (global) + PG[g] (smem), relu,
        //      fp16 -> fragment-major H
        #pragma unroll
        for (int ml = 0; ml < 2; ml++) {
            const int r0 = 32 * mg + 16 * ml + g4;
            const int mf = 2 * mg + ml;          // m-fragment index 0..3
            const float* p0 = g_PD + (size_t)sBD[r0] * 128;
            const float* p1 = g_PD + (size_t)sBD[r0 + 8] * 128;
            const float* e0 = sPG + sG[r0] * 128;
            const float* e1 = sPG + sG[r0 + 8] * 128;
            #pragma unroll
            for (int j = 0; j < 2; j++) {
                const int s2 = 2 * ng + j;       // layer-2 k-step
                const int ce = 32 * ng + 16 * j + 2 * t4;   // nl = 2j
                const int co = ce + 8;                      // nl = 2j+1
                const float2 d0e = *(const float2*)(p0 + ce);
                const float2 d1e = *(const float2*)(p1 + ce);
                const float2 d0o = *(const float2*)(p0 + co);
                const float2 d1o = *(const float2*)(p1 + co);
                const float2 g0e = *(const float2*)(e0 + ce);
                const float2 g1e = *(const float2*)(e1 + ce);
                const float2 g0o = *(const float2*)(e0 + co);
                const float2 g1o = *(const float2*)(e1 + co);
                uint4 hv;
                hv.x = pack_h2(fmaxf(acc[ml][2*j][0] + d0e.x + g0e.x, 0.f),
                               fmaxf(acc[ml][2*j][1] + d0e.y + g0e.y, 0.f));
                hv.y = pack_h2(fmaxf(acc[ml][2*j][2] + d1e.x + g1e.x, 0.f),
                               fmaxf(acc[ml][2*j][3] + d1e.y + g1e.y, 0.f));
                hv.z = pack_h2(fmaxf(acc[ml][2*j+1][0] + d0o.x + g0o.x, 0.f),
                               fmaxf(acc[ml][2*j+1][1] + d0o.y + g0o.y, 0.f));
                hv.w = pack_h2(fmaxf(acc[ml][2*j+1][2] + d1o.x + g1o.x, 0.f),
                               fmaxf(acc[ml][2*j+1][3] + d1o.y + g1o.y, 0.f));
                ((uint4*)sH)[(s2 * 4 + mf) * 32 + lane] = hv;
            }
        }
        hbar(barid);   // bar 2: H ready

        // ---------------- layer 2: 8 k-steps, A via LDS.128 ----------------
        float ac2[2][2][4];
        #pragma unroll
        for (int a = 0; a < 2; a++)
            #pragma unroll
            for (int b = 0; b < 2; b++)
                #pragma unroll
                for (int w = 0; w < 4; w++) ac2[a][b][w] = 0.f;

        #pragma unroll
        for (int s = 0; s < KS2; s++) {
            const uint4 a0v = ((const uint4*)sH)[(s * 4 + 2 * mg) * 32 + lane];
            const uint4 a1v = ((const uint4*)sH)[(s * 4 + 2 * mg + 1) * 32 + lane];
            const uint4 bq  = ((const uint4*)(smem + SM_W2F))[(s * 4 + ng) * 32 + lane];
            mma_f16(ac2[0][0][0], ac2[0][0][1], ac2[0][0][2], ac2[0][0][3],
                    a0v.x, a0v.y, a0v.z, a0v.w, bq.x, bq.y);
            mma_f16(ac2[0][1][0], ac2[0][1][1], ac2[0][1][2], ac2[0][1][3],
                    a0v.x, a0v.y, a0v.z, a0v.w, bq.z, bq.w);
            mma_f16(ac2[1][0][0], ac2[1][0][1], ac2[1][0][2], ac2[1][0][3],
                    a1v.x, a1v.y, a1v.z, a1v.w, bq.x, bq.y);
            mma_f16(ac2[1][1][0], ac2[1][1][1], ac2[1][1][2], ac2[1][1][3],
                    a1v.x, a1v.y, a1v.z, a1v.w, bq.z, bq.w);
        }

        // ---- epilogue 2: +b2, relu, dot W3, reduce ----
        #pragma unroll
        for (int ml = 0; ml < 2; ml++) {
            float p0 = 0.f, p1 = 0.f;
            #pragma unroll
            for (int nl = 0; nl < 2; nl++) {
                const int col0 = 16 * ng + 8 * nl + 2 * t4;
                const float2 bb = *(const float2*)(sB2 + col0);
                const float2 ww = *(const float2*)(sW3 + col0);
                p0 += fmaxf(ac2[ml][nl][0] + bb.x, 0.f) * ww.x
                    + fmaxf(ac2[ml][nl][1] + bb.y, 0.f) * ww.y;
                p1 += fmaxf(ac2[ml][nl][2] + bb.x, 0.f) * ww.x
                    + fmaxf(ac2[ml][nl][3] + bb.y, 0.f) * ww.y;
            }
            p0 += __shfl_xor_sync(0xffffffffu, p0, 1);
            p0 += __shfl_xor_sync(0xffffffffu, p0, 2);
            p1 += __shfl_xor_sync(0xffffffffu, p1, 1);
            p1 += __shfl_xor_sync(0xffffffffu, p1, 2);
            if (t4 == 0) {
                const int r0 = 32 * mg + 16 * ml + g4;
                sPt[r0 * 4 + ng]       = p0;
                sPt[(r0 + 8) * 4 + ng] = p1;
            }
        }
        hbar(barid);   // bar 3: partials ready

        if (htid < 64) {
            const float4 p = ((const float4*)sPt)[htid];
            const int go = tile * TILE + htid;
            if (go < M) out[go] = p.x + p.y + p.z + p.w + b3v;
        }

        cidx = nidx; cbd = nbd; cgg = ngg;
    }
}

// ---------------------------------------------------------------------------
extern "C" void kernel_launch(void* const* d_in, const int* in_sizes, int n_in,
                              void* d_out, int out_size) {
    const float* x   = (const float*)d_in[0];
    const float* hn  = (const float*)d_in[1];
    const float* hd  = (const float*)d_in[2];
    const float* hg  = (const float*)d_in[3];
    const float* W1  = (const float*)d_in[4];
    const float* b1  = (const float*)d_in[5];
    const float* W2  = (const float*)d_in[6];
    const float* b2  = (const float*)d_in[7];
    const float* W3  = (const float*)d_in[8];
    const float* b3  = (const float*)d_in[9];
    const int* sidx  = (const int*)d_in[10];
    const int* batch = (const int*)d_in[11];
    const int* nsa   = (const int*)d_in[12];
    float* out = (float*)d_out;

    const int M = in_sizes[10];
    const int G = in_sizes[12];
    int D = in_sizes[2] / 64;
    if (D > 1024) D = 1024;
    int Gc = G; if (Gc > 16) Gc = 16;
    const int ntiles = (M + TILE - 1) / TILE;

    static int sms = 0;
    if (sms == 0) {
        cudaDeviceGetAttribute(&sms, cudaDevAttrMultiProcessorCount, 0);
        cudaFuncSetAttribute(stage_policy_kernel,
                             cudaFuncAttributeMaxDynamicSharedMemorySize, SMEM_TOTAL);
        if (sms <= 0) sms = 148;
    }
    const int half_tiles = (ntiles + 1) / 2;
    const int grid = (half_tiles < sms) ? half_tiles : sms;

    precompute_pdg<<<D + Gc, 128>>>(hd, hg, W1, b1, D, Gc);
    stage_policy_kernel<<<grid, 512, SMEM_TOTAL>>>(
        x, hn, W1, W2, b2, W3, b3, sidx, batch, nsa, out, M, G, ntiles);
}